// round 15
// baseline (speedup 1.0000x reference)
#include <cuda_runtime.h>

// RNN_13855564496941: Euler RNN, T=1024, B=4096, H=50.
// R15: 3 cols/warp (between R12's 4 and R11's 2) -> 1366 one-warp CTAs,
//   ~2.31 warps/SMSP with 6 independent FFMA2 chains per warp.
//   Group A = 2 cols, cross-packed PA/QA exactly as R12 (best known).
//   Group C = 1 col, row-packed RC=(h_r,h_{r+1}); its acts stored
//   PRE-DUPLICATED {a_r,a_r,a_s,a_s} so both multiplicands are aligned
//   f32x2 sub-pairs (zero movs; costs 1 extra LDS.128/k, L1 has headroom).
//   B=4096=3*1365+1: CTA 1365 clamps colbase to 4093; overlapped cols are
//   recomputed in identical op order -> bitwise-identical duplicate stores.
//   Jrec@1 folded into bias; tanh.approx; one __syncwarp/step; outputs
//   staged in 3 scalar sOut planes, flushed by 24 lanes every 8 steps.

namespace {
constexpr int T_STEPS = 1024;
constexpr int B_DIM   = 4096;
constexpr int H_DIM   = 50;
constexpr int KPAIR   = 25;
constexpr int GRID    = 1366;
constexpr float DT    = 0.1f;
constexpr float OMDT  = 0.9f;
}

__device__ __forceinline__ float2 ffma2(float2 a, float2 b, float2 c) {
    unsigned long long A, B, C, D;
    __builtin_memcpy(&A, &a, 8);
    __builtin_memcpy(&B, &b, 8);
    __builtin_memcpy(&C, &c, 8);
    asm("fma.rn.f32x2 %0, %1, %2, %3;" : "=l"(D) : "l"(A), "l"(B), "l"(C));
    float2 d;
    __builtin_memcpy(&d, &D, 8);
    return d;
}

__device__ __forceinline__ float2 fadd2(float2 a, float2 b) {
    unsigned long long A, B, D;
    __builtin_memcpy(&A, &a, 8);
    __builtin_memcpy(&B, &b, 8);
    asm("add.rn.f32x2 %0, %1, %2;" : "=l"(D) : "l"(A), "l"(B));
    float2 d;
    __builtin_memcpy(&d, &D, 8);
    return d;
}

__device__ __forceinline__ float tanh_fast(float x) {
    float y;
    asm("tanh.approx.f32 %0, %1;" : "=f"(y) : "f"(x));
    return y;
}

__global__ __launch_bounds__(32, 10) void rnn_persist(
    const float* __restrict__ inpt,   // (T, B)
    const float* __restrict__ Jin,    // (H, 1)
    const float* __restrict__ Jrec,   // (H, H)
    const float* __restrict__ Jout,   // (1, H)
    const float* __restrict__ bias,   // (H, 1)
    const float* __restrict__ h0,     // (H, B)
    float* __restrict__ out)          // (T, B)
{
    __shared__ float4 sActA[2][32];    // A group: {a_r_c0, a_r_c1, a_s_c0, a_s_c1}
    __shared__ float4 sActC[2][32];    // C group: {a_r, a_r, a_s, a_s} (pre-dup)
    __shared__ float  sOut[3][8][33];  // [col][slot][lane], padded

    const int lane = threadIdx.x & 31;
    const int r    = 2 * lane;
    const bool valid = (lane < KPAIR);
    int cb = blockIdx.x * 3;
    if (cb > B_DIM - 3) cb = B_DIM - 3;     // CTA 1365: overlap (bitwise-identical)

    // weights + folded bias: bs = dt*bias + dt*Jrec@1
    float2 w[H_DIM];
    float2 bs = valid ? make_float2(DT * bias[r], DT * bias[r + 1]) : make_float2(0.f, 0.f);
    #pragma unroll
    for (int j = 0; j < H_DIM; j++) {
        float a = valid ? DT * Jrec[r * H_DIM + j]       : 0.0f;
        float b = valid ? DT * Jrec[(r + 1) * H_DIM + j] : 0.0f;
        w[j] = make_float2(a, b);
        bs = fadd2(bs, w[j]);
    }

    const float2 jin = valid ? make_float2(DT * Jin[r], DT * Jin[r + 1]) : make_float2(0.f, 0.f);
    const float2 jo  = valid ? make_float2(Jout[r],     Jout[r + 1])     : make_float2(0.f, 0.f);

    // state: A cross-packed PA=(h_r_c0,h_s_c1), QA=(h_r_c1,h_s_c0); C row-packed RC=(h_r_c2,h_s_c2)
    float2 PA, QA, RC;
    {
        float h_r0 = valid ? h0[r * B_DIM + cb]           : 0.f;
        float h_r1 = valid ? h0[r * B_DIM + cb + 1]       : 0.f;
        float h_r2 = valid ? h0[r * B_DIM + cb + 2]       : 0.f;
        float h_s0 = valid ? h0[(r + 1) * B_DIM + cb]     : 0.f;
        float h_s1 = valid ? h0[(r + 1) * B_DIM + cb + 1] : 0.f;
        float h_s2 = valid ? h0[(r + 1) * B_DIM + cb + 2] : 0.f;
        PA = make_float2(h_r0, h_s1);
        QA = make_float2(h_r1, h_s0);
        RC = make_float2(h_r2, h_s2);
    }

    const float* xptr = inpt + cb;
    float x0 = xptr[0], x1 = xptr[1], x2 = xptr[2];
    int p = 0;

    for (int t = 0; t < T_STEPS; t++) {
        float x0n = 0.f, x1n = 0.f, x2n = 0.f;
        if (t + 1 < T_STEPS) {
            x0n = xptr[B_DIM];
            x1n = xptr[B_DIM + 1];
            x2n = xptr[B_DIM + 2];
        }
        xptr += B_DIM;

        // acts
        sActA[p][lane] = make_float4(tanh_fast(PA.x), tanh_fast(QA.x),
                                     tanh_fast(QA.y), tanh_fast(PA.y));
        {
            float ar = tanh_fast(RC.x);
            float as = tanh_fast(RC.y);
            sActC[p][lane] = make_float4(ar, ar, as, as);
        }

        // base terms before the barrier
        const float2 om = make_float2(OMDT, OMDT);
        PA = ffma2(om, PA, ffma2(jin, make_float2(x0, x1), bs));
        QA = ffma2(om, QA, ffma2(jin, make_float2(x1, x0), bs));
        RC = ffma2(om, RC, ffma2(jin, make_float2(x2, x2), bs));

        __syncwarp();

        // batched output flush (steps t-8..t-1): lanes 0..23, 8 rows x 3 cols
        if ((t & 7) == 0 && t > 0 && lane < 24) {
            int c = lane >> 3, L = lane & 7;
            float s0 = sOut[c][L][0];
            float s1 = sOut[c][L][1];
            #pragma unroll
            for (int l = 2; l < KPAIR; l += 2) {
                s0 += sOut[c][L][l];
                if (l + 1 < KPAIR) s1 += sOut[c][L][l + 1];
            }
            out[(t - 8 + L) * B_DIM + cb + c] = s0 + s1;
        }

        // matvec: per k, 2 LDS.128 feed 6 FFMA2 across 3 independent chains
        #pragma unroll
        for (int k = 0; k < KPAIR; k++) {
            float4 avA = sActA[p][k];
            float4 avC = sActC[p][k];
            PA = ffma2(w[2 * k],     make_float2(avA.x, avA.y), PA);
            QA = ffma2(w[2 * k],     make_float2(avA.y, avA.x), QA);
            RC = ffma2(w[2 * k],     make_float2(avC.x, avC.y), RC);
            PA = ffma2(w[2 * k + 1], make_float2(avA.z, avA.w), PA);
            QA = ffma2(w[2 * k + 1], make_float2(avA.w, avA.z), QA);
            RC = ffma2(w[2 * k + 1], make_float2(avC.z, avC.w), RC);
        }

        // stage Jout partials (3 scalar planes)
        sOut[0][t & 7][lane] = fmaf(jo.x, PA.x, jo.y * QA.y);
        sOut[1][t & 7][lane] = fmaf(jo.x, QA.x, jo.y * PA.y);
        sOut[2][t & 7][lane] = fmaf(jo.x, RC.x, jo.y * RC.y);

        x0 = x0n; x1 = x1n; x2 = x2n;
        p ^= 1;
    }

    // final flush (steps 1016..1023)
    __syncwarp();
    if (lane < 24) {
        int c = lane >> 3, L = lane & 7;
        float s0 = sOut[c][L][0];
        float s1 = sOut[c][L][1];
        #pragma unroll
        for (int l = 2; l < KPAIR; l += 2) {
            s0 += sOut[c][L][l];
            if (l + 1 < KPAIR) s1 += sOut[c][L][l + 1];
        }
        out[(T_STEPS - 8 + L) * B_DIM + cb + c] = s0 + s1;
    }
}

extern "C" void kernel_launch(void* const* d_in, const int* in_sizes, int n_in,
                              void* d_out, int out_size) {
    const float* inpt = (const float*)d_in[0];
    const float* Jin  = (const float*)d_in[1];
    const float* Jrec = (const float*)d_in[2];
    const float* Jout = (const float*)d_in[3];
    const float* bias = (const float*)d_in[4];
    const float* h0   = (const float*)d_in[5];
    float* out = (float*)d_out;

    rnn_persist<<<GRID, 32>>>(inpt, Jin, Jrec, Jout, bias, h0, out);
}

// round 16
// speedup vs baseline: 1.1327x; 1.1327x over previous
#include <cuda_runtime.h>

// RNN_13855564496941: Euler RNN, T=1024, B=4096, H=50.
// R16 = R12 (best, 644us) + pure-ILP surgery:
//   (a) each of the 4 FFMA2 chains split even/odd-k -> 8 independent chains
//       of depth 25 (was 50); merged with 4 fadd2 at step end.
//   (b) __launch_bounds__(32) with no minBlocks cap: grid=1024 stays fully
//       resident up to 292 regs, so ptxas can widen its LDS batch window.
//   Else byte-for-byte R12: 1024 one-warp CTAs, 2 groups x 2 cols sharing
//   one 50-f32x2 weight copy, Jrec@1 folded into bias, non-duplicated act
//   quads (1 LDS.128 per 2 j per group), tanh.approx, one __syncwarp/step,
//   batched sOut flush every 8 steps.

namespace {
constexpr int T_STEPS = 1024;
constexpr int B_DIM   = 4096;
constexpr int H_DIM   = 50;
constexpr int KPAIR   = 25;        // float4 act entries (2 rows each)
constexpr int GRID    = B_DIM / 4; // 1024 CTAs, 4 cols each
constexpr float DT    = 0.1f;
constexpr float OMDT  = 0.9f;
}

__device__ __forceinline__ float2 ffma2(float2 a, float2 b, float2 c) {
    unsigned long long A, B, C, D;
    __builtin_memcpy(&A, &a, 8);
    __builtin_memcpy(&B, &b, 8);
    __builtin_memcpy(&C, &c, 8);
    asm("fma.rn.f32x2 %0, %1, %2, %3;" : "=l"(D) : "l"(A), "l"(B), "l"(C));
    float2 d;
    __builtin_memcpy(&d, &D, 8);
    return d;
}

__device__ __forceinline__ float2 fadd2(float2 a, float2 b) {
    unsigned long long A, B, D;
    __builtin_memcpy(&A, &a, 8);
    __builtin_memcpy(&B, &b, 8);
    asm("add.rn.f32x2 %0, %1, %2;" : "=l"(D) : "l"(A), "l"(B));
    float2 d;
    __builtin_memcpy(&d, &D, 8);
    return d;
}

__device__ __forceinline__ float tanh_fast(float x) {
    float y;
    asm("tanh.approx.f32 %0, %1;" : "=f"(y) : "f"(x));
    return y;
}

__global__ __launch_bounds__(32) void rnn_persist(
    const float* __restrict__ inpt,   // (T, B)
    const float* __restrict__ Jin,    // (H, 1)
    const float* __restrict__ Jrec,   // (H, H)
    const float* __restrict__ Jout,   // (1, H)
    const float* __restrict__ bias,   // (H, 1)
    const float* __restrict__ h0,     // (H, B)
    float* __restrict__ out)          // (T, B)
{
    __shared__ float4 sAct[2][2][32];    // [buf][group][lane], non-duplicated
    __shared__ float2 sOut[8][2][33];    // [slot][group][lane], padded rows

    const int lane = threadIdx.x & 31;
    const int r    = 2 * lane;
    const bool valid = (lane < KPAIR);
    const int gc   = blockIdx.x * 4;     // group A: gc,gc+1; group B: gc+2,gc+3

    // weights + folded bias: bs = dt*bias + dt*Jrec@1 (row sums of w)
    float2 w[H_DIM];
    float2 bs = valid ? make_float2(DT * bias[r], DT * bias[r + 1]) : make_float2(0.f, 0.f);
    #pragma unroll
    for (int j = 0; j < H_DIM; j++) {
        float a = valid ? DT * Jrec[r * H_DIM + j]       : 0.0f;
        float b = valid ? DT * Jrec[(r + 1) * H_DIM + j] : 0.0f;
        w[j] = make_float2(a, b);
        bs = fadd2(bs, w[j]);
    }

    const float2 jin = valid ? make_float2(DT * Jin[r], DT * Jin[r + 1]) : make_float2(0.f, 0.f);
    const float2 jo  = valid ? make_float2(Jout[r],     Jout[r + 1])     : make_float2(0.f, 0.f);

    // cross-packed state per group: P=(h[r][c0], h[r+1][c1]), Q=(h[r][c1], h[r+1][c0])
    float2 PA, QA, PB, QB;
    {
        float4 ra = valid ? *reinterpret_cast<const float4*>(&h0[r * B_DIM + gc])
                          : make_float4(0.f, 0.f, 0.f, 0.f);
        float4 rb = valid ? *reinterpret_cast<const float4*>(&h0[(r + 1) * B_DIM + gc])
                          : make_float4(0.f, 0.f, 0.f, 0.f);
        PA = make_float2(ra.x, rb.y);  QA = make_float2(ra.y, rb.x);
        PB = make_float2(ra.z, rb.w);  QB = make_float2(ra.w, rb.z);
    }

    const float* xptr = inpt + gc;
    float4 x4 = *reinterpret_cast<const float4*>(xptr);   // x_0 for all 4 cols
    int p = 0;

    for (int t = 0; t < T_STEPS; t++) {
        float4 x4n = make_float4(0.f, 0.f, 0.f, 0.f);
        if (t + 1 < T_STEPS)
            x4n = *reinterpret_cast<const float4*>(xptr + B_DIM);
        xptr += B_DIM;

        // acts = tanh(h): {a_r_c0, a_r_c1, a_{r+1}_c0, a_{r+1}_c1}
        sAct[p][0][lane] = make_float4(tanh_fast(PA.x), tanh_fast(QA.x),
                                       tanh_fast(QA.y), tanh_fast(PA.y));
        sAct[p][1][lane] = make_float4(tanh_fast(PB.x), tanh_fast(QB.x),
                                       tanh_fast(QB.y), tanh_fast(PB.y));

        // base terms (local-only) before the barrier
        const float2 om = make_float2(OMDT, OMDT);
        PA = ffma2(om, PA, ffma2(jin, make_float2(x4.x, x4.y), bs));
        QA = ffma2(om, QA, ffma2(jin, make_float2(x4.y, x4.x), bs));
        PB = ffma2(om, PB, ffma2(jin, make_float2(x4.z, x4.w), bs));
        QB = ffma2(om, QB, ffma2(jin, make_float2(x4.w, x4.z), bs));

        __syncwarp();

        // batched output flush (steps t-8..t-1), 16 lanes: 8 rows x 2 groups
        if ((t & 7) == 0 && t > 0 && lane < 16) {
            int g = lane >> 3, L = lane & 7;
            float2 s0 = sOut[L][g][0];
            float2 s1 = sOut[L][g][1];
            #pragma unroll
            for (int l = 2; l < KPAIR; l += 2) {
                s0 = fadd2(s0, sOut[L][g][l]);
                if (l + 1 < KPAIR) s1 = fadd2(s1, sOut[L][g][l + 1]);
            }
            *reinterpret_cast<float2*>(&out[(t - 8 + L) * B_DIM + gc + 2 * g]) = fadd2(s0, s1);
        }

        // matvec: per k, 2 broadcast LDS.128 + 8 FFMA2; even/odd k go to
        // separate accumulators -> 8 independent chains of depth 25
        float2 PA1 = make_float2(0.f, 0.f), QA1 = make_float2(0.f, 0.f);
        float2 PB1 = make_float2(0.f, 0.f), QB1 = make_float2(0.f, 0.f);
        #pragma unroll
        for (int k = 0; k < KPAIR; k += 2) {
            float4 avA = sAct[p][0][k];
            float4 avB = sAct[p][1][k];
            PA = ffma2(w[2 * k],     make_float2(avA.x, avA.y), PA);
            QA = ffma2(w[2 * k],     make_float2(avA.y, avA.x), QA);
            PB = ffma2(w[2 * k],     make_float2(avB.x, avB.y), PB);
            QB = ffma2(w[2 * k],     make_float2(avB.y, avB.x), QB);
            PA = ffma2(w[2 * k + 1], make_float2(avA.z, avA.w), PA);
            QA = ffma2(w[2 * k + 1], make_float2(avA.w, avA.z), QA);
            PB = ffma2(w[2 * k + 1], make_float2(avB.z, avB.w), PB);
            QB = ffma2(w[2 * k + 1], make_float2(avB.w, avB.z), QB);
            if (k + 1 < KPAIR) {
                float4 cvA = sAct[p][0][k + 1];
                float4 cvB = sAct[p][1][k + 1];
                PA1 = ffma2(w[2 * k + 2], make_float2(cvA.x, cvA.y), PA1);
                QA1 = ffma2(w[2 * k + 2], make_float2(cvA.y, cvA.x), QA1);
                PB1 = ffma2(w[2 * k + 2], make_float2(cvB.x, cvB.y), PB1);
                QB1 = ffma2(w[2 * k + 2], make_float2(cvB.y, cvB.x), QB1);
                PA1 = ffma2(w[2 * k + 3], make_float2(cvA.z, cvA.w), PA1);
                QA1 = ffma2(w[2 * k + 3], make_float2(cvA.w, cvA.z), QA1);
                PB1 = ffma2(w[2 * k + 3], make_float2(cvB.z, cvB.w), PB1);
                QB1 = ffma2(w[2 * k + 3], make_float2(cvB.w, cvB.z), QB1);
            }
        }
        PA = fadd2(PA, PA1);
        QA = fadd2(QA, QA1);
        PB = fadd2(PB, PB1);
        QB = fadd2(QB, QB1);

        // stage Jout partials: colpair (c0,c1) = (jo.(P.x,Q.y), jo.(Q.x,P.y))
        sOut[t & 7][0][lane] = make_float2(fmaf(jo.x, PA.x, jo.y * QA.y),
                                           fmaf(jo.x, QA.x, jo.y * PA.y));
        sOut[t & 7][1][lane] = make_float2(fmaf(jo.x, PB.x, jo.y * QB.y),
                                           fmaf(jo.x, QB.x, jo.y * PB.y));

        x4 = x4n;
        p ^= 1;
    }

    // final flush (steps 1016..1023)
    __syncwarp();
    if (lane < 16) {
        int g = lane >> 3, L = lane & 7;
        float2 s0 = sOut[L][g][0];
        float2 s1 = sOut[L][g][1];
        #pragma unroll
        for (int l = 2; l < KPAIR; l += 2) {
            s0 = fadd2(s0, sOut[L][g][l]);
            if (l + 1 < KPAIR) s1 = fadd2(s1, sOut[L][g][l + 1]);
        }
        *reinterpret_cast<float2*>(&out[(T_STEPS - 8 + L) * B_DIM + gc + 2 * g]) = fadd2(s0, s1);
    }
}

extern "C" void kernel_launch(void* const* d_in, const int* in_sizes, int n_in,
                              void* d_out, int out_size) {
    const float* inpt = (const float*)d_in[0];
    const float* Jin  = (const float*)d_in[1];
    const float* Jrec = (const float*)d_in[2];
    const float* Jout = (const float*)d_in[3];
    const float* bias = (const float*)d_in[4];
    const float* h0   = (const float*)d_in[5];
    float* out = (float*)d_out;

    rnn_persist<<<GRID, 32>>>(inpt, Jin, Jrec, Jout, bias, h0, out);
}

// round 17
// speedup vs baseline: 2.4101x; 2.1279x over previous
#include <cuda_runtime.h>

// RNN_13855564496941: Euler RNN, T=1024, B=4096, H=50.
// R17: tensor-core (tf32 mma.sync.m16n8k8) warp-autonomous version.
//   Warp = 8 batch cols, 512 one-warp CTAs. W padded to 64x64; dt*Jrec held
//   as tf32 A-fragments in 128 regs. State h lives in D-fragment layout
//   (4 m-tiles x 4 f32). Per step: tanh -> cvt.tf32 -> STS act tile [64][8]
//   -> __syncwarp -> base init in-place -> 16 LDS.32 B-frags -> 32 mma.sync
//   -> Jout partials staged in sOut, flushed every 8 steps (R12 pattern).
//   Jrec@1 folded into bias'; padded rows/cols are exact zeros.

namespace {
constexpr int T_STEPS = 1024;
constexpr int B_DIM   = 4096;
constexpr int H_DIM   = 50;
constexpr int NCOL    = 8;             // batch cols per warp
constexpr int GRID    = B_DIM / NCOL;  // 512 CTAs
constexpr float DT    = 0.1f;
constexpr float OMDT  = 0.9f;
}

__device__ __forceinline__ float tanh_fast(float x) {
    float y;
    asm("tanh.approx.f32 %0, %1;" : "=f"(y) : "f"(x));
    return y;
}

__device__ __forceinline__ unsigned cvt_tf32(float x) {
    unsigned u;
    asm("cvt.rna.tf32.f32 %0, %1;" : "=r"(u) : "f"(x));
    return u;
}

__device__ __forceinline__ void mma_tf32(float* d, const unsigned* a,
                                         unsigned b0, unsigned b1) {
    asm("mma.sync.aligned.m16n8k8.row.col.f32.tf32.tf32.f32 "
        "{%0,%1,%2,%3}, {%4,%5,%6,%7}, {%8,%9}, {%0,%1,%2,%3};"
        : "+f"(d[0]), "+f"(d[1]), "+f"(d[2]), "+f"(d[3])
        : "r"(a[0]), "r"(a[1]), "r"(a[2]), "r"(a[3]), "r"(b0), "r"(b1));
}

__global__ __launch_bounds__(32) void rnn_tc(
    const float* __restrict__ inpt,   // (T, B)
    const float* __restrict__ Jin,    // (H, 1)
    const float* __restrict__ Jrec,   // (H, H)
    const float* __restrict__ Jout,   // (1, H)
    const float* __restrict__ bias,   // (H, 1)
    const float* __restrict__ h0,     // (H, B)
    float* __restrict__ out)          // (T, B)
{
    __shared__ unsigned sAct[2][64][8];   // tf32 act bits, [buf][k-row][n-col]
    __shared__ float2   sOut[8][33];      // [slot][lane], padded vs bank conflicts

    const int lane = threadIdx.x & 31;
    const int gid  = lane >> 2;           // 0..7
    const int tg   = lane & 3;            // 0..3
    const int gc   = blockIdx.x * NCOL;

    // ---- weight A-fragments: wa[mt][kt][4], tf32 of dt*Jrec (padded 0) ----
    unsigned wa[4][8][4];
    #pragma unroll
    for (int mt = 0; mt < 4; mt++) {
        int rA = mt * 16 + gid, rB = rA + 8;
        #pragma unroll
        for (int kt = 0; kt < 8; kt++) {
            int cA = kt * 8 + tg, cB = cA + 4;
            float w00 = (rA < H_DIM && cA < H_DIM) ? DT * Jrec[rA * H_DIM + cA] : 0.f;
            float w10 = (rB < H_DIM && cA < H_DIM) ? DT * Jrec[rB * H_DIM + cA] : 0.f;
            float w01 = (rA < H_DIM && cB < H_DIM) ? DT * Jrec[rA * H_DIM + cB] : 0.f;
            float w11 = (rB < H_DIM && cB < H_DIM) ? DT * Jrec[rB * H_DIM + cB] : 0.f;
            wa[mt][kt][0] = cvt_tf32(w00);
            wa[mt][kt][1] = cvt_tf32(w10);
            wa[mt][kt][2] = cvt_tf32(w01);
            wa[mt][kt][3] = cvt_tf32(w11);
        }
    }

    // ---- per-row constants for the 8 owned rows (mt x {A,B}) ----
    float jinr[8], bsr[8], jor[8];
    #pragma unroll
    for (int mt = 0; mt < 4; mt++) {
        #pragma unroll
        for (int hf = 0; hf < 2; hf++) {
            int r = mt * 16 + gid + 8 * hf;
            float ji = 0.f, bo = 0.f, jj = 0.f;
            if (r < H_DIM) {
                ji = DT * Jin[r];
                jj = Jout[r];
                float s = bias[r];
                for (int j = 0; j < H_DIM; j++) s += Jrec[r * H_DIM + j];
                bo = DT * s;                 // dt*bias + dt*Jrec@1 fold
            }
            jinr[mt * 2 + hf] = ji;
            bsr[mt * 2 + hf]  = bo;
            jor[mt * 2 + hf]  = jj;
        }
    }

    // ---- state in D-fragment layout: d[mt] = {(rA,c0),(rA,c1),(rB,c0),(rB,c1)} ----
    const int c0 = 2 * tg, c1 = c0 + 1;
    float d[4][4];
    #pragma unroll
    for (int mt = 0; mt < 4; mt++) {
        int rA = mt * 16 + gid, rB = rA + 8;
        d[mt][0] = (rA < H_DIM) ? h0[rA * B_DIM + gc + c0] : 0.f;
        d[mt][1] = (rA < H_DIM) ? h0[rA * B_DIM + gc + c1] : 0.f;
        d[mt][2] = (rB < H_DIM) ? h0[rB * B_DIM + gc + c0] : 0.f;
        d[mt][3] = (rB < H_DIM) ? h0[rB * B_DIM + gc + c1] : 0.f;
    }

    const float* xptr = inpt + gc + c0;
    float2 x = *reinterpret_cast<const float2*>(xptr);   // x_t for cols c0,c1
    int p = 0;

    for (int t = 0; t < T_STEPS; t++) {
        float2 xN = make_float2(0.f, 0.f);
        if (t + 1 < T_STEPS)
            xN = *reinterpret_cast<const float2*>(xptr + B_DIM);
        xptr += B_DIM;

        // acts: tanh -> tf32, stored as [row][col] tile (conflict-free uint2 STS)
        #pragma unroll
        for (int mt = 0; mt < 4; mt++) {
            int rA = mt * 16 + gid, rB = rA + 8;
            uint2 uA = make_uint2(cvt_tf32(tanh_fast(d[mt][0])),
                                  cvt_tf32(tanh_fast(d[mt][1])));
            uint2 uB = make_uint2(cvt_tf32(tanh_fast(d[mt][2])),
                                  cvt_tf32(tanh_fast(d[mt][3])));
            *reinterpret_cast<uint2*>(&sAct[p][rA][c0]) = uA;
            *reinterpret_cast<uint2*>(&sAct[p][rB][c0]) = uB;
        }

        // base init in place: d = 0.9 h + dt*Jin*x + bias'
        #pragma unroll
        for (int mt = 0; mt < 4; mt++) {
            float jA = jinr[mt * 2], jB = jinr[mt * 2 + 1];
            float bA = bsr[mt * 2],  bB = bsr[mt * 2 + 1];
            d[mt][0] = fmaf(OMDT, d[mt][0], fmaf(jA, x.x, bA));
            d[mt][1] = fmaf(OMDT, d[mt][1], fmaf(jA, x.y, bA));
            d[mt][2] = fmaf(OMDT, d[mt][2], fmaf(jB, x.x, bB));
            d[mt][3] = fmaf(OMDT, d[mt][3], fmaf(jB, x.y, bB));
        }

        __syncwarp();

        // batched output flush (steps t-8..t-1): 32 tasks = 8 slots x 4 colpairs
        if ((t & 7) == 0 && t > 0) {
            int slot = lane >> 2, tc = lane & 3;
            float2 s = sOut[slot][tc];
            #pragma unroll
            for (int g = 1; g < 8; g++) {
                float2 v = sOut[slot][g * 4 + tc];
                s.x += v.x; s.y += v.y;
            }
            *reinterpret_cast<float2*>(&out[(t - 8 + slot) * B_DIM + gc + 2 * tc]) = s;
        }

        // B-fragments + MMA: per kt, 2 LDS.32 (conflict-free) + 4 mma.sync
        #pragma unroll
        for (int kt = 0; kt < 8; kt++) {
            unsigned b0 = sAct[p][kt * 8 + tg][gid];
            unsigned b1 = sAct[p][kt * 8 + tg + 4][gid];
            #pragma unroll
            for (int mt = 0; mt < 4; mt++)
                mma_tf32(d[mt], wa[mt][kt], b0, b1);
        }

        // Jout partials for cols (c0, c1)
        float2 pp = make_float2(0.f, 0.f);
        #pragma unroll
        for (int mt = 0; mt < 4; mt++) {
            pp.x = fmaf(jor[mt * 2], d[mt][0], fmaf(jor[mt * 2 + 1], d[mt][2], pp.x));
            pp.y = fmaf(jor[mt * 2], d[mt][1], fmaf(jor[mt * 2 + 1], d[mt][3], pp.y));
        }
        sOut[t & 7][lane] = pp;

        x = xN;
        p ^= 1;
    }

    // final flush (steps T-8..T-1)
    __syncwarp();
    {
        int slot = lane >> 2, tc = lane & 3;
        float2 s = sOut[slot][tc];
        #pragma unroll
        for (int g = 1; g < 8; g++) {
            float2 v = sOut[slot][g * 4 + tc];
            s.x += v.x; s.y += v.y;
        }
        *reinterpret_cast<float2*>(&out[(T_STEPS - 8 + slot) * B_DIM + gc + 2 * tc]) = s;
    }
}

extern "C" void kernel_launch(void* const* d_in, const int* in_sizes, int n_in,
                              void* d_out, int out_size) {
    const float* inpt = (const float*)d_in[0];
    const float* Jin  = (const float*)d_in[1];
    const float* Jrec = (const float*)d_in[2];
    const float* Jout = (const float*)d_in[3];
    const float* bias = (const float*)d_in[4];
    const float* h0   = (const float*)d_in[5];
    float* out = (float*)d_out;

    rnn_tc<<<GRID, 32>>>(inpt, Jin, Jrec, Jout, bias, h0, out);
}